// round 6
// baseline (speedup 1.0000x reference)
#include <cuda_runtime.h>

#define NCHAN  3
#define H      512
#define W      512
#define KS     21
#define KTAPS  (KS * KS)          // 441

// CTA tile: 64 output cols x 64 output rows, 128 threads = 4 warps.
// thread = (colg, py): colg 0..3 -> 16 cols each; py 0..31 -> rows Yb+2py, +2py+1.
// Input window: rows Yb-10..Yb+73 (84), cols Xb-12..Xb+76 (89 floats, 44 pairs).
#define TROWS  84
#define TPAIRS 48                 // pairs padded for XOR swizzle
#define PLANE  (TROWS * TPAIRS)

typedef unsigned long long ull;

__device__ __forceinline__ void ffma2(ull& d, ull a, ull b) {
    asm("fma.rn.f32x2 %0, %1, %2, %0;" : "+l"(d) : "l"(a), "l"(b));
}
__device__ __forceinline__ ull pk(float lo, float hi) {
    ull r; asm("mov.b64 %0, {%1, %2};" : "=l"(r) : "f"(lo), "f"(hi)); return r;
}
__device__ __forceinline__ void unpk(ull v, float& lo, float& hi) {
    asm("mov.b64 {%0, %1}, %2;" : "=f"(lo), "=f"(hi) : "l"(v));
}

// dynamic smem: [A plane][B plane][kp 484 float2]
#define SMEM_BYTES (2 * PLANE * 8 + 22 * 22 * 8)

__global__ __launch_bounds__(128, 3) void conv_kernel(const float* __restrict__ x,
                                                      const float* __restrict__ d_k,
                                                      float* __restrict__ d_out) {
    extern __shared__ __align__(16) ull sm[];
    ull* smA = sm;
    ull* smB = sm + PLANE;
    float2* kp = reinterpret_cast<float2*>(sm + 2 * PLANE);

    const int tid = threadIdx.x;
    const int img = blockIdx.z;
    const int Xb  = blockIdx.x * 64;
    const int Yb  = blockIdx.y * 64;

    // fused diagonal tap table: kp[r][jj] = (k[r][jj-1], k[r-1][jj]); OOR -> 0
    const float* kptr = d_k + (size_t)(img / NCHAN) * KTAPS;
    for (int i = tid; i < 22 * 22; i += 128) {
        int r  = i / 22;
        int jj = i % 22;
        float lo = (r <= 20 && jj >= 1) ? kptr[r * KS + jj - 1] : 0.f;
        float hi = (r >= 1 && jj <= 20) ? kptr[(r - 1) * KS + jj] : 0.f;
        kp[i] = make_float2(lo, hi);
    }

    // ---- load window into dual swizzled planes ------------------------------
    const float* ximg = x + (size_t)img * H * W;
    for (int i = tid; i < TROWS * 22; i += 128) {
        int row = i / 22;
        int q   = i % 22;
        int gy  = Yb - 10 + row;
        int gx  = Xb - 12 + 4 * q;
        bool rok = ((unsigned)gy < H);
        float4 v = make_float4(0.f, 0.f, 0.f, 0.f);
        if (rok && gx >= 0 && gx <= W - 4)
            v = *reinterpret_cast<const float4*>(ximg + (size_t)gy * W + gx);
        float e4 = 0.f;
        int gx4 = gx + 4;
        if (rok && gx4 >= 0 && gx4 < W)
            e4 = ximg[(size_t)gy * W + gx4];

        int sw2  = ((row >> 1) & 7) << 1;
        int base = (2 * q) ^ sw2;
        ull* arow = smA + row * TPAIRS;
        ull* brow = smB + row * TPAIRS;
        *reinterpret_cast<ulonglong2*>(arow + base) =
            make_ulonglong2(pk(v.x, v.y), pk(v.z, v.w));
        *reinterpret_cast<ulonglong2*>(brow + base) =
            make_ulonglong2(pk(v.y, v.z), pk(v.w, e4));
    }
    __syncthreads();

    // ---- main loop: 16 cols x 2 output rows (f32x2 lanes) per thread --------
    const int colg = tid >> 5;
    const int py   = tid & 31;
    const int p0   = colg * 8;

    ull acc[16];
#pragma unroll
    for (int c = 0; c < 16; ++c) acc[c] = 0ull;

    // tap prefetch pipeline: kk always holds the tap-pair about to be used
    ulonglong2 kk = *reinterpret_cast<const ulonglong2*>(kp);

#pragma unroll 2
    for (int r = 0; r < 22; ++r) {
        const int rowi = 2 * py + r;
        const int sw2  = ((rowi >> 1) & 7) << 1;
        const ull* Ar = smA + rowi * TPAIRS;
        const ull* Br = smB + rowi * TPAIRS;

        // data for this row: 20 pairs per plane
        ull e[20], b[20];
#pragma unroll
        for (int t = 0; t < 10; ++t) {
            int s = (p0 + 2 * t) ^ sw2;
            ulonglong2 va = *reinterpret_cast<const ulonglong2*>(Ar + s);
            ulonglong2 vb = *reinterpret_cast<const ulonglong2*>(Br + s);
            e[2 * t] = va.x; e[2 * t + 1] = va.y;
            b[2 * t] = vb.x; b[2 * t + 1] = vb.y;
        }

        const ulonglong2* kr =
            reinterpret_cast<const ulonglong2*>(kp + r * 22);
        const ulonglong2* krn =
            reinterpret_cast<const ulonglong2*>(kp + (r < 21 ? (r + 1) * 22 : 0));

#pragma unroll
        for (int jh = 0; jh < 11; ++jh) {
            // prefetch next tap pair while computing with current one
            ulonglong2 kkn = (jh < 10) ? kr[jh + 1] : krn[0];
#pragma unroll
            for (int c = 0; c < 16; ++c) {            // jj = 2jh
                ull a = (c & 1) ? e[jh + (c + 1) / 2] : b[jh + c / 2];
                ffma2(acc[c], a, kk.x);
            }
#pragma unroll
            for (int c = 0; c < 16; ++c) {            // jj = 2jh+1
                ull a = (c & 1) ? b[jh + (c + 1) / 2] : e[jh + c / 2 + 1];
                ffma2(acc[c], a, kk.y);
            }
            kk = kkn;
        }
    }

    // ---- store: 2 rows x 16 cols --------------------------------------------
    float lo[16], hi[16];
#pragma unroll
    for (int c = 0; c < 16; ++c) unpk(acc[c], lo[c], hi[c]);

    float* op = d_out + ((size_t)img * H + Yb + 2 * py) * W + Xb + colg * 16;
#pragma unroll
    for (int j = 0; j < 4; ++j) {
        reinterpret_cast<float4*>(op)[j] =
            make_float4(lo[4 * j], lo[4 * j + 1], lo[4 * j + 2], lo[4 * j + 3]);
        reinterpret_cast<float4*>(op + W)[j] =
            make_float4(hi[4 * j], hi[4 * j + 1], hi[4 * j + 2], hi[4 * j + 3]);
    }
}

extern "C" void kernel_launch(void* const* d_in, const int* in_sizes, int n_in,
                              void* d_out, int out_size) {
    const float* x = (const float*)d_in[0];   // (32,3,512,512) fp32
    const float* k = (const float*)d_in[1];   // (32,1,21,21)  fp32
    float* out = (float*)d_out;

    cudaFuncSetAttribute(conv_kernel,
                         cudaFuncAttributeMaxDynamicSharedMemorySize, SMEM_BYTES);

    dim3 grid(W / 64, H / 64, 96);            // (8, 8, 96)
    conv_kernel<<<grid, 128, SMEM_BYTES>>>(x, k, out);
}